// round 11
// baseline (speedup 1.0000x reference)
#include <cuda_runtime.h>
#include <cstdint>

// L1Attn: out[b,i,j,h] = -(1/8) * sum_d |q[b,j,h,d] - k[b,i,h,d]|
// B=8, S=1024, H=8, D=64. Output [B,S,S,H] (i = keys, j = queries).
//
// i-pair packed f32x2: k stored transposed ks2[h][d][i0..7] so LDS.128 yields
// packed (k_i, k_i+1); accumulators pack output pairs (16 ull = 32 regs,
// half of R10) -> regs ~80 -> 3 blocks/SM = 24 warps at the same LDS/term.
// q scalar from padded smem, duplicated into packed regs per (u,d).

namespace {
constexpr int S  = 1024;
constexpr int H  = 8;
constexpr int D  = 64;
constexpr int NT = 256;
constexpr int TI = 8;      // i per block (4 packed pairs per thread)
constexpr int JB = 128;    // j per block (32 slots x 4 u)
constexpr int CD = 8;      // d per q chunk
constexpr int NC = D / CD;             // 8 chunks
constexpr int QROW = 12;               // 8 d + 4 pad (3*row mod 8 covers quads)
constexpr int KPLANE = 516;            // 64 d * 8 i + 4 pad floats (2064B = 129 quads)
constexpr int KS_FLOATS = H * KPLANE;          // 4128  (16512 B)
constexpr int QS_FLOATS = JB * H * QROW;       // 12288 (49152 B)
constexpr unsigned SMEM_BYTES = (KS_FLOATS + QS_FLOATS) * 4;  // 65664

typedef unsigned long long ull;

__device__ __forceinline__ ull subx2(ull a, ull b) {
    ull r;
    asm("sub.rn.f32x2 %0, %1, %2;" : "=l"(r) : "l"(a), "l"(b));
    return r;
}
__device__ __forceinline__ ull addx2(ull a, ull b) {
    ull r;
    asm("add.rn.f32x2 %0, %1, %2;" : "=l"(r) : "l"(a), "l"(b));
    return r;
}
__device__ __forceinline__ ull dupf(float f) {
    ull r;
    asm("mov.b64 %0, {%1, %1};" : "=l"(r) : "f"(f));
    return r;
}
__device__ __forceinline__ void cp16(uint32_t dst_smem, const float* src) {
    asm volatile("cp.async.cg.shared.global [%0], [%1], 16;"
                 :: "r"(dst_smem), "l"(src));
}
}  // namespace

__global__ void __launch_bounds__(NT, 3) l1attn_kernel(
    const float* __restrict__ qg,
    const float* __restrict__ kg,
    float* __restrict__ out)
{
    extern __shared__ __align__(16) float smf[];
    float* ks2 = smf;               // [8 h][64 d][8 i] plane stride 516
    float* qs  = smf + KS_FLOATS;   // [1024 rows][12], row = jj*8 + h

    const int t  = threadIdx.x;
    const int j0 = blockIdx.x * JB;
    const int i0 = blockIdx.y * TI;
    const int b  = blockIdx.z;

    const float* qtile = qg + ((size_t)b * S + j0) * (size_t)(H * D);
    const uint32_t qs_base = (uint32_t)__cvta_generic_to_shared(qs);

    // ---- Issue q chunk 0 staging (cp.async into padded rows) ----
    #pragma unroll
    for (int r = 0; r < 8; r++) {
        int p   = t + r * NT;      // piece 0..2047
        int row = p >> 1;          // 0..1023
        int sg  = p & 1;           // 16B seg within 8-d chunk
        cp16(qs_base + (row * QROW + sg * 4) * 4, qtile + row * D + sg * 4);
    }
    asm volatile("cp.async.commit_group;" ::: "memory");

    // ---- Stage k transposed: ks2[h][d][i] ----
    {
        const float* kb = kg + ((size_t)b * S + i0) * (size_t)(H * D);
        #pragma unroll
        for (int r = 0; r < 4; r++) {
            int p    = t + r * NT;     // float4 piece 0..1023
            int row  = p >> 4;         // (i*8 + h), 0..63
            int dseg = p & 15;         // 4-float d group
            int i    = row >> 3;
            int h    = row & 7;
            float4 v = *reinterpret_cast<const float4*>(kb + row * D + dseg * 4);
            float* dst = ks2 + h * KPLANE + (dseg * 4) * TI + i;
            dst[0 * TI] = v.x;
            dst[1 * TI] = v.y;
            dst[2 * TI] = v.z;
            dst[3 * TI] = v.w;
        }
    }
    asm volatile("cp.async.wait_group 0;" ::: "memory");
    __syncthreads();

    const int h  = t & 7;
    const int jl = (t >> 3) & 3;
    const int w  = t >> 5;
    const int jbase = j0 + w * 16 + jl;          // u adds 4 j
    const int qrow0 = (w * 16 + jl) * 8 + h;     // u adds 4 j = 32 rows

    const ull MSK = 0x7FFFFFFF7FFFFFFFULL;

    ull acc[4][4];   // [i-pair][u], lo = i=2p, hi = i=2p+1
    #pragma unroll
    for (int p = 0; p < 4; p++)
        #pragma unroll
        for (int u = 0; u < 4; u++) acc[p][u] = 0ULL;

    #pragma unroll 1
    for (int cc = 0; cc < NC; cc++) {          // 8-d chunk
        #pragma unroll
        for (int s = 0; s < 2; s++) {          // 4 d per step
            // q: one LDS.128 per u -> 4 scalar d values
            float4 qf[4];
            #pragma unroll
            for (int u = 0; u < 4; u++)
                qf[u] = *reinterpret_cast<const float4*>(
                    qs + (qrow0 + u * 32) * QROW + s * 4);

            const float* kp = ks2 + h * KPLANE + (cc * CD + s * 4) * TI;
            #pragma unroll
            for (int d = 0; d < 4; d++) {
                ulonglong2 ka = *reinterpret_cast<const ulonglong2*>(kp + d * TI);
                ulonglong2 kb2 = *reinterpret_cast<const ulonglong2*>(kp + d * TI + 4);
                ull kd[4] = {ka.x, ka.y, kb2.x, kb2.y};   // i-pairs 0..3
                #pragma unroll
                for (int u = 0; u < 4; u++) {
                    float qsc = (d == 0) ? qf[u].x : (d == 1) ? qf[u].y
                              : (d == 2) ? qf[u].z : qf[u].w;
                    ull qq = dupf(qsc);
                    #pragma unroll
                    for (int p = 0; p < 4; p++) {
                        ull tt = subx2(kd[p], qq) & MSK;   // |k-q| for (2p, 2p+1)
                        acc[p][u] = addx2(acc[p][u], tt);
                    }
                }
            }
        }
        // ---- Stage next q chunk (single buffer: fence both sides) ----
        if (cc + 1 < NC) {
            __syncthreads();
            const float* qc = qtile + (cc + 1) * CD;
            #pragma unroll
            for (int r = 0; r < 8; r++) {
                int p   = t + r * NT;
                int row = p >> 1;
                int sg  = p & 1;
                cp16(qs_base + (row * QROW + sg * 4) * 4, qc + row * D + sg * 4);
            }
            asm volatile("cp.async.commit_group;" ::: "memory");
            asm volatile("cp.async.wait_group 0;" ::: "memory");
            __syncthreads();
        }
    }

    // ---- Epilogue: unpack pair halves, scale, coalesced stores ----
    const float scale = -0.125f;  // -1/sqrt(64)
    #pragma unroll
    for (int p = 0; p < 4; p++) {
        #pragma unroll
        for (int half = 0; half < 2; half++) {
            const int i = 2 * p + half;
            const size_t ob = (((size_t)b * S + (i0 + i)) * S + jbase) * H + h;
            #pragma unroll
            for (int u = 0; u < 4; u++) {
                unsigned int bits = half ? (unsigned int)(acc[p][u] >> 32)
                                         : (unsigned int)(acc[p][u] & 0xffffffffu);
                out[ob + (size_t)u * (4 * H)] = __uint_as_float(bits) * scale;
            }
        }
    }
}

extern "C" void kernel_launch(void* const* d_in, const int* in_sizes, int n_in,
                              void* d_out, int out_size) {
    const float* q = (const float*)d_in[0];
    const float* k = (const float*)d_in[1];
    float* out     = (float*)d_out;

    cudaFuncSetAttribute(l1attn_kernel,
                         cudaFuncAttributeMaxDynamicSharedMemorySize, SMEM_BYTES);

    const int B = in_sizes[0] / (S * H * D);  // = 8
    dim3 grid(S / JB, S / TI, B);
    l1attn_kernel<<<grid, NT, SMEM_BYTES>>>(q, k, out);
}